// round 9
// baseline (speedup 1.0000x reference)
#include <cuda_runtime.h>
#include <cuda_bf16.h>
#include <cstdint>

// ---------------- static scratch (allocation-free rule) ----------------
#define V_MAX     262144
#define B_MAX     8
#define TILE      4096
#define TILES_MAX 64
#define SW        256          // super-window (positions per pipeline step)

__device__ unsigned long long g_recA[V_MAX];
__device__ unsigned long long g_recB[V_MAX];
__device__ unsigned int       g_hist[B_MAX * TILES_MAX * 256];
__device__ int                g_order[V_MAX];
__device__ int                g_selLocal[V_MAX];
__device__ int                g_ggLocal[V_MAX];
__device__ int                g_segCount[B_MAX];
__device__ int                g_rsn[B_MAX + 1];

// ---------------- cp.async helpers ----------------
__device__ __forceinline__ void cpa16(void* dst, const void* src) {
    unsigned d = (unsigned)__cvta_generic_to_shared(dst);
    asm volatile("cp.async.cg.shared.global [%0], [%1], 16;\n" :: "r"(d), "l"(src));
}
__device__ __forceinline__ void cpa4(void* dst, const void* src) {
    unsigned d = (unsigned)__cvta_generic_to_shared(dst);
    asm volatile("cp.async.ca.shared.global [%0], [%1], 4;\n" :: "r"(d), "l"(src));
}
#define CP_COMMIT() asm volatile("cp.async.commit_group;\n" ::: "memory")
#define CP_WAIT0()  asm volatile("cp.async.wait_group 0;\n" ::: "memory")

// ---------------- sort: pack ----------------
__global__ void packK(const float* __restrict__ hier, int V) {
    int i = blockIdx.x * blockDim.x + threadIdx.x;
    if (i >= V) return;
    unsigned bits = __float_as_uint(hier[i]);
    unsigned m = (unsigned)(-(int)(bits >> 31)) | 0x80000000u;   // order-preserving
    unsigned u = bits ^ m;
    g_recA[i] = ((unsigned long long)u << 32) | (unsigned)i;
}

// ---------------- sort: per-(segment,tile) histogram ----------------
__global__ void histK(int dir, int shift, int TILES, const int* __restrict__ rs) {
    const unsigned long long* in = dir ? g_recB : g_recA;
    int seg = blockIdx.y;
    int s0 = rs[seg], s1 = rs[seg + 1];
    __shared__ unsigned int h[256];
    if (threadIdx.x < 256) h[threadIdx.x] = 0u;
    __syncthreads();
    int base = s0 + blockIdx.x * TILE;
    int n = min(TILE, s1 - base);
    for (int p = threadIdx.x; p < n; p += blockDim.x) {
        unsigned d = (unsigned)(in[base + p] >> shift) & 0xFFu;
        atomicAdd(&h[d], 1u);
    }
    __syncthreads();
    if (threadIdx.x < 256)
        g_hist[(seg * TILES + blockIdx.x) * 256 + threadIdx.x] = h[threadIdx.x];
}

// ---------------- sort: scan (per segment) ----------------
__global__ void scanK(int TILES, const int* __restrict__ rs) {
    int seg = blockIdx.x;
    int s0 = rs[seg];
    int d = threadIdx.x;            // 256 threads, one digit each
    unsigned run = 0;
    for (int t = 0; t < TILES; t++) {
        unsigned idx = (seg * TILES + t) * 256 + d;
        unsigned c = g_hist[idx];
        g_hist[idx] = run;
        run += c;
    }
    __shared__ unsigned tot[256];
    __shared__ unsigned start[256];
    tot[d] = run;
    __syncthreads();
    if (d == 0) {
        unsigned a = 0;
        for (int q = 0; q < 256; q++) { start[q] = a; a += tot[q]; }
    }
    __syncthreads();
    unsigned add = start[d] + (unsigned)s0;
    for (int t = 0; t < TILES; t++)
        g_hist[(seg * TILES + t) * 256 + d] += add;
}

// ---------------- sort: stable scatter ----------------
__global__ void scatterK(int dir, int shift, int TILES, const int* __restrict__ rs) {
    const unsigned long long* in  = dir ? g_recB : g_recA;
    unsigned long long*       out = dir ? g_recA : g_recB;
    int seg = blockIdx.y;
    int s0 = rs[seg], s1 = rs[seg + 1];
    int base = s0 + blockIdx.x * TILE;
    int n = min(TILE, s1 - base);
    if (n <= 0) return;

    __shared__ unsigned s_ofs[256];
    __shared__ unsigned int s_dig32[TILE / 4 + 1];
    __shared__ unsigned short s_rank[TILE + 8];
    unsigned char* s_dig = (unsigned char*)s_dig32;

    if (threadIdx.x < 256)
        s_ofs[threadIdx.x] = g_hist[(seg * TILES + blockIdx.x) * 256 + threadIdx.x];

    unsigned long long r[TILE / 256];
#pragma unroll
    for (int k = 0; k < TILE / 256; k++) {
        int p = k * 256 + threadIdx.x;
        if (p < n) {
            r[k] = in[base + p];
            s_dig[p] = (unsigned char)((r[k] >> shift) & 0xFF);
        }
    }
    if (threadIdx.x < 4) {
        int q = n + threadIdx.x;
        if (q < TILE + 4) s_dig[q] = 0;
    }
    __syncthreads();

    // stable local rank: thread d scans all digits (smem broadcast reads)
    {
        unsigned char d = (unsigned char)threadIdx.x;
        unsigned c = 0;
        int nw = (n + 3) >> 2;
        for (int q = 0; q < nw; q++) {
            unsigned w = s_dig32[q];
#pragma unroll
            for (int b = 0; b < 4; b++) {
                if (((w >> (8 * b)) & 0xFFu) == (unsigned)d) {
                    s_rank[q * 4 + b] = (unsigned short)c;
                    c++;
                }
            }
        }
    }
    __syncthreads();

#pragma unroll
    for (int k = 0; k < TILE / 256; k++) {
        int p = k * 256 + threadIdx.x;
        if (p < n) {
            unsigned d = s_dig[p];
            out[s_ofs[d] + s_rank[p]] = r[k];
        }
    }
}

__global__ void extractK(int V) {
    int i = blockIdx.x * blockDim.x + threadIdx.x;
    if (i < V) g_order[i] = (int)(g_recA[i] & 0xFFFFFFFFull);
}

// sel output is float32: fill with -1.0f
__global__ void fillSelK(float* __restrict__ sel, int V) {
    int i = blockIdx.x * blockDim.x + threadIdx.x;
    if (i < V) sel[i] = -1.0f;
}

// ---------------- clustering: one block per segment ----------------
// Barrier-synchronized cp.async double-buffer pipeline. No spins anywhere:
// every loop is bounded, every barrier reached by all 1024 threads.
//   rbuf : 2 buffers x SW rows x K ints  (neighbour rows; 4 threads/row,
//          each thread copies 64 B = 4 x cp.async.16B)   [K==64 fast path]
//   obuf : 4 buffers x SW ints           (order values, 4-step lookahead)
// At iteration s: wait last group; barrier; issue rows(s+1) using order(s+1),
// issue order(s+3); warp 0 walks super-window s from smem.
// Local cluster ids go into g_ggLocal (int scratch); float conversion is done
// in fixK (output dtype is float32).
__global__ void __launch_bounds__(1024, 1)
clusterK(const int* __restrict__ neighs, const int* __restrict__ rs,
         int V, int K) {
    extern __shared__ int smemArr[];
    int seg = blockIdx.x;
    int s0 = rs[seg], s1 = rs[seg + 1];
    int segLen = s1 - s0;
    int bwMax = (V + 31) >> 5;
    int bw = (segLen + 31) >> 5;

    unsigned int* bitmap = (unsigned int*)smemArr;   // bwMax words allocated
    int* obuf = smemArr + bwMax;                     // 4*SW ints
    int* rbuf = obuf + 4 * SW;                       // 2*SW*K ints (K==64 path)

    int tid = threadIdx.x, lane = tid & 31, wid = tid >> 5;
    bool useRing = (K == 64);

    for (int w = tid; w < bw; w += blockDim.x) bitmap[w] = 0u;
    __syncthreads();

    int nSW = (segLen + SW - 1) / SW;
    int myrow = tid >> 2;              // 256 rows, 4 threads per row
    int mybase = (tid & 3) * 16;       // int offset of this thread's 64-byte slice

    // ---- prologue ----
    // group 1: order(0)
    if (nSW > 0 && tid < SW) {
        int j = s0 + tid;
        if (j < s1) cpa4(&obuf[tid], &g_order[j]);
    }
    CP_COMMIT();
    CP_WAIT0();
    __syncthreads();
    // group 2: rows(0) [needs order(0)], order(1), order(2)
    if (useRing && nSW > 0) {
        int j = s0 + myrow;
        if (j < s1) {
            int v = obuf[myrow];
#pragma unroll
            for (int c = 0; c < 4; c++)
                cpa16(rbuf + myrow * K + mybase + c * 4,
                      neighs + (size_t)v * K + mybase + c * 4);
        }
    }
    if (tid < SW) {
        for (int w = 1; w <= 2; w++) {
            if (w < nSW) {
                int j = s0 + w * SW + tid;
                if (j < s1) cpa4(&obuf[(w & 3) * SW + tid], &g_order[j]);
            }
        }
    }
    CP_COMMIT();

    // ---- main loop ----
    int cnt = 0;
    for (int s = 0; s < nSW; s++) {
        CP_WAIT0();          // completes group issued last iteration (rows s, order s+2)
        __syncthreads();     // data visible to all; warp0 done with walk s-1

        // issue rows(s+1) + order(s+3)
        int wN = s + 1;
        if (useRing && wN < nSW) {
            int j = s0 + wN * SW + myrow;
            if (j < s1) {
                int v = obuf[(wN & 3) * SW + myrow];
#pragma unroll
                for (int c = 0; c < 4; c++)
                    cpa16(rbuf + (wN & 1) * SW * K + myrow * K + mybase + c * 4,
                          neighs + (size_t)v * K + mybase + c * 4);
            }
        }
        int wO = s + 3;
        if (wO < nSW && tid < SW) {
            int j = s0 + wO * SW + tid;
            if (j < s1) cpa4(&obuf[(wO & 3) * SW + tid], &g_order[j]);
        }
        CP_COMMIT();

        // ---- warp 0 walks super-window s ----
        if (wid == 0) {
            int base = s0 + s * SW;
            int lim = min(SW, s1 - base);
            int* rows = rbuf + (s & 1) * SW * K;
            int* ord  = obuf + (s & 3) * SW;

            for (int w0 = 0; w0 < lim; w0 += 32) {
                int m = min(32, lim - w0);
                int v = (lane < m) ? ord[w0 + lane] : 0;

                bool a = false;
                if (lane < m) {
                    int rel = v - s0;
                    a = !((bitmap[rel >> 5] >> (rel & 31)) & 1u);
                }
                unsigned alive = __ballot_sync(0xFFFFFFFFu, a);

                while (alive) {
                    int l = __ffs(alive) - 1;
                    int cv = __shfl_sync(0xFFFFFFFFu, v, l);
                    const int* row = useRing ? (rows + (w0 + l) * K)
                                             : (neighs + (size_t)cv * K);

                    if (lane == 0) {
                        int rel = cv - s0;
                        atomicOr(&bitmap[rel >> 5], 1u << (rel & 31));
                        g_ggLocal[cv] = cnt;
                        g_selLocal[s0 + cnt] = cv;
                    }
                    __syncwarp();

                    for (int t = lane; t < K; t += 32) {
                        int n = row[t];
                        if (n >= 0 && n != cv) {
                            int rel = n - s0;
                            if ((unsigned)rel < (unsigned)segLen) {
                                unsigned old = atomicOr(&bitmap[rel >> 5],
                                                        1u << (rel & 31));
                                if (!((old >> (rel & 31)) & 1u)) g_ggLocal[n] = cnt;
                            }
                        }
                    }
                    __syncwarp();
                    cnt++;

                    bool a2 = false;
                    if (lane < m && lane > l) {
                        int rel = v - s0;
                        a2 = !((bitmap[rel >> 5] >> (rel & 31)) & 1u);
                    }
                    alive = __ballot_sync(0xFFFFFFFFu, a2);
                }
            }
        }
    }
    if (wid == 0 && lane == 0) g_segCount[seg] = cnt;
}

// ---------------- finalize (float32 outputs) ----------------
__global__ void finalizeK(float* __restrict__ rsn, int B) {
    int a = 0;
    rsn[0] = 0.0f; g_rsn[0] = 0;
    for (int s = 0; s < B; s++) {
        a += g_segCount[s];
        rsn[s + 1] = (float)a;
        g_rsn[s + 1] = a;
    }
}

__global__ void fixK(const int* __restrict__ rs, float* __restrict__ sel,
                     float* __restrict__ gg, int V, int B) {
    int i = blockIdx.x * blockDim.x + threadIdx.x;
    if (i >= V) return;
    int s = 0;
    while (s < B - 1 && i >= rs[s + 1]) s++;
    gg[i] = (float)(g_ggLocal[i] + g_rsn[s]);      // local -> global cluster id
    int t = i - rs[s];
    if (t < g_segCount[s]) sel[g_rsn[s] + t] = (float)g_selLocal[i];
}

// ---------------- launch ----------------
extern "C" void kernel_launch(void* const* d_in, const int* in_sizes, int n_in,
                              void* d_out, int out_size) {
    // identify inputs by size: largest=neighs, middle=hier, smallest=row_splits
    long s[3] = { in_sizes[0], in_sizes[1], in_sizes[2] };
    int big = 0, small = 0;
    for (int i = 1; i < 3; i++) {
        if (s[i] > s[big]) big = i;
        if (s[i] < s[small]) small = i;
    }
    int mid = 3 - big - small;
    const int*   neighs = (const int*)d_in[big];
    const float* hier   = (const float*)d_in[mid];
    const int*   rs     = (const int*)d_in[small];

    int V = in_sizes[mid];
    int K = in_sizes[big] / V;
    int B = in_sizes[small] - 1;
    if (V > V_MAX || B > B_MAX || B < 1) return;

    float* out = (float*)d_out;
    float* sel = out;
    float* rsn = out + V;
    float* gg  = out + V + B + 1;

    int TILES = (V + TILE - 1) / TILE;
    if (TILES > TILES_MAX) return;

    int nb = (V + 255) / 256;
    packK<<<nb, 256>>>(hier, V);

    for (int p = 0; p < 4; p++) {
        int dir = p & 1;                  // 0: A->B, 1: B->A  (4 passes end in A)
        int shift = 32 + 8 * p;
        dim3 grid(TILES, B);
        histK<<<grid, 256>>>(dir, shift, TILES, rs);
        scanK<<<B, 256>>>(TILES, rs);
        scatterK<<<grid, 256>>>(dir, shift, TILES, rs);
    }
    extractK<<<nb, 256>>>(V);
    fillSelK<<<nb, 256>>>(sel, V);

    int bwMax = (V + 31) >> 5;
    bool useRing = (K == 64);
    size_t smemBytes = ((size_t)bwMax + 4 * SW) * 4
                     + (useRing ? (size_t)2 * SW * K * 4 : 0);

    // Set the >48KB smem opt-in only outside graph capture (attribute persists;
    // the un-captured correctness call always runs first).
    cudaStreamCaptureStatus cs = cudaStreamCaptureStatusNone;
    cudaStreamIsCapturing((cudaStream_t)0, &cs);
    if (cs == cudaStreamCaptureStatusNone) {
        cudaFuncSetAttribute(clusterK, cudaFuncAttributeMaxDynamicSharedMemorySize,
                             (int)smemBytes);
    }

    clusterK<<<B, 1024, smemBytes>>>(neighs, rs, V, K);

    finalizeK<<<1, 1>>>(rsn, B);
    fixK<<<nb, 256>>>(rs, sel, gg, V, B);
}

// round 10
// speedup vs baseline: 1.4053x; 1.4053x over previous
#include <cuda_runtime.h>
#include <cuda_bf16.h>
#include <cstdint>

// ---------------- static scratch (allocation-free rule) ----------------
#define V_MAX     262144
#define B_MAX     8
#define TILE      4096
#define TILES_MAX 64
#define SW        256          // super-window (positions per pipeline step)

__device__ unsigned long long g_recA[V_MAX];
__device__ unsigned long long g_recB[V_MAX];
__device__ unsigned int       g_hist[B_MAX * TILES_MAX * 256];
__device__ int                g_order[V_MAX];
__device__ int                g_selLocal[V_MAX];
__device__ int                g_ggLocal[V_MAX];
__device__ int                g_segCount[B_MAX];
__device__ int                g_rsn[B_MAX + 1];

// ---------------- cp.async helpers ----------------
__device__ __forceinline__ void cpa16(void* dst, const void* src) {
    unsigned d = (unsigned)__cvta_generic_to_shared(dst);
    asm volatile("cp.async.cg.shared.global [%0], [%1], 16;\n" :: "r"(d), "l"(src));
}
__device__ __forceinline__ void cpa4(void* dst, const void* src) {
    unsigned d = (unsigned)__cvta_generic_to_shared(dst);
    asm volatile("cp.async.ca.shared.global [%0], [%1], 4;\n" :: "r"(d), "l"(src));
}
#define CP_COMMIT() asm volatile("cp.async.commit_group;\n" ::: "memory")
#define CP_WAIT0()  asm volatile("cp.async.wait_group 0;\n" ::: "memory")

// ---------------- sort: pack ----------------
__global__ void packK(const float* __restrict__ hier, int V) {
    int i = blockIdx.x * blockDim.x + threadIdx.x;
    if (i >= V) return;
    unsigned bits = __float_as_uint(hier[i]);
    unsigned m = (unsigned)(-(int)(bits >> 31)) | 0x80000000u;   // order-preserving
    unsigned u = bits ^ m;
    g_recA[i] = ((unsigned long long)u << 32) | (unsigned)i;
}

// ---------------- sort: per-(segment,tile) histogram ----------------
__global__ void histK(int dir, int shift, int TILES, const int* __restrict__ rs) {
    const unsigned long long* in = dir ? g_recB : g_recA;
    int seg = blockIdx.y;
    int s0 = rs[seg], s1 = rs[seg + 1];
    __shared__ unsigned int h[256];
    if (threadIdx.x < 256) h[threadIdx.x] = 0u;
    __syncthreads();
    int base = s0 + blockIdx.x * TILE;
    int n = min(TILE, s1 - base);
    for (int p = threadIdx.x; p < n; p += blockDim.x) {
        unsigned d = (unsigned)(in[base + p] >> shift) & 0xFFu;
        atomicAdd(&h[d], 1u);
    }
    __syncthreads();
    if (threadIdx.x < 256)
        g_hist[(seg * TILES + blockIdx.x) * 256 + threadIdx.x] = h[threadIdx.x];
}

// ---------------- sort: scan (per segment) ----------------
__global__ void scanK(int TILES, const int* __restrict__ rs) {
    int seg = blockIdx.x;
    int s0 = rs[seg];
    int d = threadIdx.x;            // 256 threads, one digit each
    unsigned run = 0;
    for (int t = 0; t < TILES; t++) {
        unsigned idx = (seg * TILES + t) * 256 + d;
        unsigned c = g_hist[idx];
        g_hist[idx] = run;
        run += c;
    }
    __shared__ unsigned tot[256];
    __shared__ unsigned start[256];
    tot[d] = run;
    __syncthreads();
    if (d == 0) {
        unsigned a = 0;
        for (int q = 0; q < 256; q++) { start[q] = a; a += tot[q]; }
    }
    __syncthreads();
    unsigned add = start[d] + (unsigned)s0;
    for (int t = 0; t < TILES; t++)
        g_hist[(seg * TILES + t) * 256 + d] += add;
}

// ---------------- sort: stable scatter (match_any warp ranking) ----------------
// Each warp owns a 512-element chunk (16 groups of 32, in element order).
// Within a group: __match_any_sync on the digit -> stable within-group rank.
// Group leader bumps per-(warp,digit) counter; cross-chunk prefix per digit.
__global__ void scatterK(int dir, int shift, int TILES, const int* __restrict__ rs) {
    const unsigned long long* in  = dir ? g_recB : g_recA;
    unsigned long long*       out = dir ? g_recA : g_recB;
    int seg = blockIdx.y;
    int s0 = rs[seg], s1 = rs[seg + 1];
    int base = s0 + blockIdx.x * TILE;
    int n = min(TILE, s1 - base);
    if (n <= 0) return;

    __shared__ unsigned s_ofs[256];
    __shared__ unsigned s_cnt[8][256];     // per-chunk digit counters -> prefix
    int tid = threadIdx.x, lane = tid & 31, w = tid >> 5;

    if (tid < 256)
        s_ofs[tid] = g_hist[(seg * TILES + blockIdx.x) * 256 + tid];
    for (int q = tid; q < 8 * 256; q += 256)
        ((unsigned*)s_cnt)[q] = 0u;
    __syncthreads();

    unsigned long long r[16];
    unsigned short rk[16];
    unsigned char  dg[16];
    unsigned lml = (1u << lane) - 1u;

#pragma unroll
    for (int g = 0; g < 16; g++) {
        int p = w * 512 + g * 32 + lane;
        bool valid = p < n;
        unsigned d = 0x1FFu;               // sentinel groups the invalid lanes
        if (valid) {
            r[g] = in[base + p];
            d = (unsigned)(r[g] >> shift) & 0xFFu;
            dg[g] = (unsigned char)d;
        }
        unsigned mask = __match_any_sync(0xFFFFFFFFu, d);
        int leader = __ffs(mask) - 1;
        unsigned prev = 0;
        if (lane == leader && valid)
            prev = atomicAdd(&s_cnt[w][d], __popc(mask));
        prev = __shfl_sync(0xFFFFFFFFu, prev, leader);
        if (valid) rk[g] = (unsigned short)(prev + __popc(mask & lml));
    }
    __syncthreads();

    // prefix chunk counts per digit (8 chunks)
    if (tid < 256) {
        unsigned run = 0;
#pragma unroll
        for (int c = 0; c < 8; c++) {
            unsigned t = s_cnt[c][tid];
            s_cnt[c][tid] = run;
            run += t;
        }
    }
    __syncthreads();

#pragma unroll
    for (int g = 0; g < 16; g++) {
        int p = w * 512 + g * 32 + lane;
        if (p < n) {
            unsigned d = dg[g];
            out[s_ofs[d] + s_cnt[w][d] + rk[g]] = r[g];
        }
    }
}

__global__ void extractK(int V) {
    int i = blockIdx.x * blockDim.x + threadIdx.x;
    if (i < V) g_order[i] = (int)(g_recA[i] & 0xFFFFFFFFull);
}

// sel output is float32: fill with -1.0f
__global__ void fillSelK(float* __restrict__ sel, int V) {
    int i = blockIdx.x * blockDim.x + threadIdx.x;
    if (i < V) sel[i] = -1.0f;
}

// ---------------- clustering: one block per segment ----------------
// Barrier-synchronized cp.async double-buffer pipeline (bounded, no spins).
// Walk (warp 0) fast path: pre-read bitmap (plain LDS) for the free test,
// fire-and-forget atomicOr only when actually absorbing, single syncwarp per
// center, K=64 unrolled into two overlapped LDS chains.
// Exactness: all absorptions of one center write the same cnt, so duplicate
// neighbours racing on the pre-read are harmless; n==cv (self) is excluded,
// matching the reference's assigned[v]-before-free semantics.
__global__ void __launch_bounds__(1024, 1)
clusterK(const int* __restrict__ neighs, const int* __restrict__ rs,
         int V, int K) {
    extern __shared__ int smemArr[];
    int seg = blockIdx.x;
    int s0 = rs[seg], s1 = rs[seg + 1];
    int segLen = s1 - s0;
    int bwMax = (V + 31) >> 5;
    int bw = (segLen + 31) >> 5;

    unsigned int* bitmap = (unsigned int*)smemArr;   // bwMax words allocated
    int* obuf = smemArr + bwMax;                     // 4*SW ints
    int* rbuf = obuf + 4 * SW;                       // 2*SW*K ints (K==64 path)

    int tid = threadIdx.x, lane = tid & 31, wid = tid >> 5;
    bool useRing = (K == 64);

    for (int w = tid; w < bw; w += blockDim.x) bitmap[w] = 0u;
    __syncthreads();

    int nSW = (segLen + SW - 1) / SW;
    int myrow = tid >> 2;              // 256 rows, 4 threads per row
    int mybase = (tid & 3) * 16;       // int offset of this thread's 64-byte slice

    // ---- prologue ----
    if (nSW > 0 && tid < SW) {
        int j = s0 + tid;
        if (j < s1) cpa4(&obuf[tid], &g_order[j]);
    }
    CP_COMMIT();
    CP_WAIT0();
    __syncthreads();
    if (useRing && nSW > 0) {
        int j = s0 + myrow;
        if (j < s1) {
            int v = obuf[myrow];
#pragma unroll
            for (int c = 0; c < 4; c++)
                cpa16(rbuf + myrow * K + mybase + c * 4,
                      neighs + (size_t)v * K + mybase + c * 4);
        }
    }
    if (tid < SW) {
        for (int w = 1; w <= 2; w++) {
            if (w < nSW) {
                int j = s0 + w * SW + tid;
                if (j < s1) cpa4(&obuf[(w & 3) * SW + tid], &g_order[j]);
            }
        }
    }
    CP_COMMIT();

    // ---- main loop ----
    int cnt = 0;
    for (int s = 0; s < nSW; s++) {
        CP_WAIT0();
        __syncthreads();

        int wN = s + 1;
        if (useRing && wN < nSW) {
            int j = s0 + wN * SW + myrow;
            if (j < s1) {
                int v = obuf[(wN & 3) * SW + myrow];
#pragma unroll
                for (int c = 0; c < 4; c++)
                    cpa16(rbuf + (wN & 1) * SW * K + myrow * K + mybase + c * 4,
                          neighs + (size_t)v * K + mybase + c * 4);
            }
        }
        int wO = s + 3;
        if (wO < nSW && tid < SW) {
            int j = s0 + wO * SW + tid;
            if (j < s1) cpa4(&obuf[(wO & 3) * SW + tid], &g_order[j]);
        }
        CP_COMMIT();

        // ---- warp 0 walks super-window s ----
        if (wid == 0) {
            int base = s0 + s * SW;
            int lim = min(SW, s1 - base);
            int* rows = rbuf + (s & 1) * SW * K;
            int* ord  = obuf + (s & 3) * SW;

            for (int w0 = 0; w0 < lim; w0 += 32) {
                int m = min(32, lim - w0);
                int v = (lane < m) ? ord[w0 + lane] : 0;

                bool a = false;
                if (lane < m) {
                    int rel = v - s0;
                    a = !((bitmap[rel >> 5] >> (rel & 31)) & 1u);
                }
                unsigned alive = __ballot_sync(0xFFFFFFFFu, a);

                while (alive) {
                    int l = __ffs(alive) - 1;
                    int cv = __shfl_sync(0xFFFFFFFFu, v, l);
                    const int* row = useRing ? (rows + (w0 + l) * K)
                                             : (neighs + (size_t)cv * K);

                    // two overlapped neighbour loads (K == 64 over 32 lanes)
                    int n0 = row[lane];
                    int n1 = (K > 32) ? row[lane + 32] : -1;

                    if (lane == 0) {
                        int rel = cv - s0;
                        atomicOr(&bitmap[rel >> 5], 1u << (rel & 31));
                        g_ggLocal[cv] = cnt;
                        g_selLocal[s0 + cnt] = cv;
                    }

                    int r0 = n0 - s0, r1 = n1 - s0;
                    bool f0 = (n0 >= 0) && (n0 != cv) &&
                              ((unsigned)r0 < (unsigned)segLen);
                    bool f1 = (n1 >= 0) && (n1 != cv) &&
                              ((unsigned)r1 < (unsigned)segLen);
                    unsigned wb0 = f0 ? bitmap[r0 >> 5] : 1u;
                    unsigned wb1 = f1 ? bitmap[r1 >> 5] : 1u;
                    bool free0 = f0 && !((wb0 >> (r0 & 31)) & 1u);
                    bool free1 = f1 && !((wb1 >> (r1 & 31)) & 1u);
                    if (free0) {
                        atomicOr(&bitmap[r0 >> 5], 1u << (r0 & 31));
                        g_ggLocal[n0] = cnt;
                    }
                    if (free1) {
                        atomicOr(&bitmap[r1 >> 5], 1u << (r1 & 31));
                        g_ggLocal[n1] = cnt;
                    }
                    cnt++;
                    __syncwarp();

                    bool a2 = false;
                    if (lane < m && lane > l) {
                        int rel = v - s0;
                        a2 = !((bitmap[rel >> 5] >> (rel & 31)) & 1u);
                    }
                    alive = __ballot_sync(0xFFFFFFFFu, a2);
                }
            }
        }
    }
    if (wid == 0 && lane == 0) g_segCount[seg] = cnt;
}

// ---------------- finalize (float32 outputs) ----------------
__global__ void finalizeK(float* __restrict__ rsn, int B) {
    int a = 0;
    rsn[0] = 0.0f; g_rsn[0] = 0;
    for (int s = 0; s < B; s++) {
        a += g_segCount[s];
        rsn[s + 1] = (float)a;
        g_rsn[s + 1] = a;
    }
}

__global__ void fixK(const int* __restrict__ rs, float* __restrict__ sel,
                     float* __restrict__ gg, int V, int B) {
    int i = blockIdx.x * blockDim.x + threadIdx.x;
    if (i >= V) return;
    int s = 0;
    while (s < B - 1 && i >= rs[s + 1]) s++;
    gg[i] = (float)(g_ggLocal[i] + g_rsn[s]);      // local -> global cluster id
    int t = i - rs[s];
    if (t < g_segCount[s]) sel[g_rsn[s] + t] = (float)g_selLocal[i];
}

// ---------------- launch ----------------
extern "C" void kernel_launch(void* const* d_in, const int* in_sizes, int n_in,
                              void* d_out, int out_size) {
    // identify inputs by size: largest=neighs, middle=hier, smallest=row_splits
    long s[3] = { in_sizes[0], in_sizes[1], in_sizes[2] };
    int big = 0, small = 0;
    for (int i = 1; i < 3; i++) {
        if (s[i] > s[big]) big = i;
        if (s[i] < s[small]) small = i;
    }
    int mid = 3 - big - small;
    const int*   neighs = (const int*)d_in[big];
    const float* hier   = (const float*)d_in[mid];
    const int*   rs     = (const int*)d_in[small];

    int V = in_sizes[mid];
    int K = in_sizes[big] / V;
    int B = in_sizes[small] - 1;
    if (V > V_MAX || B > B_MAX || B < 1) return;

    float* out = (float*)d_out;
    float* sel = out;
    float* rsn = out + V;
    float* gg  = out + V + B + 1;

    int TILES = (V + TILE - 1) / TILE;
    if (TILES > TILES_MAX) return;

    int nb = (V + 255) / 256;
    packK<<<nb, 256>>>(hier, V);

    for (int p = 0; p < 4; p++) {
        int dir = p & 1;                  // 0: A->B, 1: B->A  (4 passes end in A)
        int shift = 32 + 8 * p;
        dim3 grid(TILES, B);
        histK<<<grid, 256>>>(dir, shift, TILES, rs);
        scanK<<<B, 256>>>(TILES, rs);
        scatterK<<<grid, 256>>>(dir, shift, TILES, rs);
    }
    extractK<<<nb, 256>>>(V);
    fillSelK<<<nb, 256>>>(sel, V);

    int bwMax = (V + 31) >> 5;
    bool useRing = (K == 64);
    size_t smemBytes = ((size_t)bwMax + 4 * SW) * 4
                     + (useRing ? (size_t)2 * SW * K * 4 : 0);

    // Set the >48KB smem opt-in only outside graph capture (attribute persists;
    // the un-captured correctness call always runs first).
    cudaStreamCaptureStatus cs = cudaStreamCaptureStatusNone;
    cudaStreamIsCapturing((cudaStream_t)0, &cs);
    if (cs == cudaStreamCaptureStatusNone) {
        cudaFuncSetAttribute(clusterK, cudaFuncAttributeMaxDynamicSharedMemorySize,
                             (int)smemBytes);
    }

    clusterK<<<B, 1024, smemBytes>>>(neighs, rs, V, K);

    finalizeK<<<1, 1>>>(rsn, B);
    fixK<<<nb, 256>>>(rs, sel, gg, V, B);
}

// round 12
// speedup vs baseline: 1.5791x; 1.1237x over previous
#include <cuda_runtime.h>
#include <cuda_bf16.h>
#include <cstdint>

// ---------------- static scratch (allocation-free rule) ----------------
#define V_MAX     262144
#define B_MAX     8
#define TILE      4096
#define TILES_MAX 64
#define SW        256          // super-window (positions per pipeline step)

__device__ unsigned long long g_recA[V_MAX];
__device__ unsigned long long g_recB[V_MAX];
__device__ unsigned int       g_hist[B_MAX * TILES_MAX * 256];
__device__ int                g_order[V_MAX];
__device__ int                g_selLocal[V_MAX];
__device__ int                g_ggLocal[V_MAX];
__device__ int                g_segCount[B_MAX];
__device__ int                g_rsn[B_MAX + 1];

// ---------------- cp.async helpers ----------------
__device__ __forceinline__ void cpa16(void* dst, const void* src) {
    unsigned d = (unsigned)__cvta_generic_to_shared(dst);
    asm volatile("cp.async.cg.shared.global [%0], [%1], 16;\n" :: "r"(d), "l"(src));
}
__device__ __forceinline__ void cpa4(void* dst, const void* src) {
    unsigned d = (unsigned)__cvta_generic_to_shared(dst);
    asm volatile("cp.async.ca.shared.global [%0], [%1], 4;\n" :: "r"(d), "l"(src));
}
#define CP_COMMIT() asm volatile("cp.async.commit_group;\n" ::: "memory")
#define CP_WAIT0()  asm volatile("cp.async.wait_group 0;\n" ::: "memory")

// ---------------- sort: pack (+ init ggLocal to INT_MAX) ----------------
__global__ void packK(const float* __restrict__ hier, int V) {
    int i = blockIdx.x * blockDim.x + threadIdx.x;
    if (i >= V) return;
    unsigned bits = __float_as_uint(hier[i]);
    unsigned m = (unsigned)(-(int)(bits >> 31)) | 0x80000000u;   // order-preserving
    unsigned u = bits ^ m;
    g_recA[i] = ((unsigned long long)u << 32) | (unsigned)i;
    g_ggLocal[i] = 0x7FFFFFFF;
}

// ---------------- sort: per-(segment,tile) histogram ----------------
__global__ void histK(int dir, int shift, int TILES, const int* __restrict__ rs) {
    const unsigned long long* in = dir ? g_recB : g_recA;
    int seg = blockIdx.y;
    int s0 = rs[seg], s1 = rs[seg + 1];
    __shared__ unsigned int h[256];
    if (threadIdx.x < 256) h[threadIdx.x] = 0u;
    __syncthreads();
    int base = s0 + blockIdx.x * TILE;
    int n = min(TILE, s1 - base);
    for (int p = threadIdx.x; p < n; p += blockDim.x) {
        unsigned d = (unsigned)(in[base + p] >> shift) & 0xFFu;
        atomicAdd(&h[d], 1u);
    }
    __syncthreads();
    if (threadIdx.x < 256)
        g_hist[(seg * TILES + blockIdx.x) * 256 + threadIdx.x] = h[threadIdx.x];
}

// ---------------- sort: scan (per segment) ----------------
__global__ void scanK(int TILES, const int* __restrict__ rs) {
    int seg = blockIdx.x;
    int s0 = rs[seg];
    int d = threadIdx.x;            // 256 threads, one digit each
    unsigned run = 0;
    for (int t = 0; t < TILES; t++) {
        unsigned idx = (seg * TILES + t) * 256 + d;
        unsigned c = g_hist[idx];
        g_hist[idx] = run;
        run += c;
    }
    __shared__ unsigned tot[256];
    __shared__ unsigned start[256];
    tot[d] = run;
    __syncthreads();
    if (d == 0) {
        unsigned a = 0;
        for (int q = 0; q < 256; q++) { start[q] = a; a += tot[q]; }
    }
    __syncthreads();
    unsigned add = start[d] + (unsigned)s0;
    for (int t = 0; t < TILES; t++)
        g_hist[(seg * TILES + t) * 256 + d] += add;
}

// ---------------- sort: stable scatter (match_any warp ranking) ----------------
__global__ void scatterK(int dir, int shift, int TILES, const int* __restrict__ rs) {
    const unsigned long long* in  = dir ? g_recB : g_recA;
    unsigned long long*       out = dir ? g_recA : g_recB;
    int seg = blockIdx.y;
    int s0 = rs[seg], s1 = rs[seg + 1];
    int base = s0 + blockIdx.x * TILE;
    int n = min(TILE, s1 - base);
    if (n <= 0) return;

    __shared__ unsigned s_ofs[256];
    __shared__ unsigned s_cnt[8][256];     // per-chunk digit counters -> prefix
    int tid = threadIdx.x, lane = tid & 31, w = tid >> 5;

    if (tid < 256)
        s_ofs[tid] = g_hist[(seg * TILES + blockIdx.x) * 256 + tid];
    for (int q = tid; q < 8 * 256; q += 256)
        ((unsigned*)s_cnt)[q] = 0u;
    __syncthreads();

    unsigned long long r[16];
    unsigned short rk[16];
    unsigned char  dg[16];
    unsigned lml = (1u << lane) - 1u;

#pragma unroll
    for (int g = 0; g < 16; g++) {
        int p = w * 512 + g * 32 + lane;
        bool valid = p < n;
        unsigned d = 0x1FFu;               // sentinel groups the invalid lanes
        if (valid) {
            r[g] = in[base + p];
            d = (unsigned)(r[g] >> shift) & 0xFFu;
            dg[g] = (unsigned char)d;
        }
        unsigned mask = __match_any_sync(0xFFFFFFFFu, d);
        int leader = __ffs(mask) - 1;
        unsigned prev = 0;
        if (lane == leader && valid)
            prev = atomicAdd(&s_cnt[w][d], __popc(mask));
        prev = __shfl_sync(0xFFFFFFFFu, prev, leader);
        if (valid) rk[g] = (unsigned short)(prev + __popc(mask & lml));
    }
    __syncthreads();

    if (tid < 256) {
        unsigned run = 0;
#pragma unroll
        for (int c = 0; c < 8; c++) {
            unsigned t = s_cnt[c][tid];
            s_cnt[c][tid] = run;
            run += t;
        }
    }
    __syncthreads();

#pragma unroll
    for (int g = 0; g < 16; g++) {
        int p = w * 512 + g * 32 + lane;
        if (p < n) {
            unsigned d = dg[g];
            out[s_ofs[d] + s_cnt[w][d] + rk[g]] = r[g];
        }
    }
}

__global__ void extractK(int V) {
    int i = blockIdx.x * blockDim.x + threadIdx.x;
    if (i < V) g_order[i] = (int)(g_recA[i] & 0xFFFFFFFFull);
}

// ---------------- clustering phase 1: centers + bitmap only ----------------
// Barrier-synchronized cp.async double-buffer pipeline (bounded, no spins).
// Phase 1 ONLY selects centers (recording g_selLocal) and maintains the
// assigned-bitmap (idempotent atomicOr; no returned-old; center's own bit is
// never needed since each vertex is a candidate exactly once). gg is computed
// exactly in phase 2 via atomicMin: gg[u] = min cnt over centers adjacent to u
// (provably equal to the reference's first-absorber semantics).
__global__ void __launch_bounds__(1024, 1)
clusterK(const int* __restrict__ neighs, const int* __restrict__ rs,
         int V, int K) {
    extern __shared__ int smemArr[];
    int seg = blockIdx.x;
    int s0 = rs[seg], s1 = rs[seg + 1];
    int segLen = s1 - s0;
    int bwMax = (V + 31) >> 5;
    int bw = (segLen + 31) >> 5;

    unsigned int* bitmap = (unsigned int*)smemArr;   // bwMax words allocated
    int* obuf = smemArr + bwMax;                     // 4*SW ints
    int* rbuf = obuf + 4 * SW;                       // 2*SW*K ints (K==64 path)

    int tid = threadIdx.x, lane = tid & 31, wid = tid >> 5;
    bool useRing = (K == 64);

    for (int w = tid; w < bw; w += blockDim.x) bitmap[w] = 0u;
    __syncthreads();

    int nSW = (segLen + SW - 1) / SW;
    int myrow = tid >> 2;              // 256 rows, 4 threads per row
    int mybase = (tid & 3) * 16;       // int offset of this thread's 64-byte slice

    // ---- prologue ----
    if (nSW > 0 && tid < SW) {
        int j = s0 + tid;
        if (j < s1) cpa4(&obuf[tid], &g_order[j]);
    }
    CP_COMMIT();
    CP_WAIT0();
    __syncthreads();
    if (useRing && nSW > 0) {
        int j = s0 + myrow;
        if (j < s1) {
            int v = obuf[myrow];
#pragma unroll
            for (int c = 0; c < 4; c++)
                cpa16(rbuf + myrow * K + mybase + c * 4,
                      neighs + (size_t)v * K + mybase + c * 4);
        }
    }
    if (tid < SW) {
        for (int w = 1; w <= 2; w++) {
            if (w < nSW) {
                int j = s0 + w * SW + tid;
                if (j < s1) cpa4(&obuf[(w & 3) * SW + tid], &g_order[j]);
            }
        }
    }
    CP_COMMIT();

    // ---- main loop ----
    int cnt = 0;
    for (int s = 0; s < nSW; s++) {
        CP_WAIT0();
        __syncthreads();

        int wN = s + 1;
        if (useRing && wN < nSW) {
            int j = s0 + wN * SW + myrow;
            if (j < s1) {
                int v = obuf[(wN & 3) * SW + myrow];
#pragma unroll
                for (int c = 0; c < 4; c++)
                    cpa16(rbuf + (wN & 1) * SW * K + myrow * K + mybase + c * 4,
                          neighs + (size_t)v * K + mybase + c * 4);
            }
        }
        int wO = s + 3;
        if (wO < nSW && tid < SW) {
            int j = s0 + wO * SW + tid;
            if (j < s1) cpa4(&obuf[(wO & 3) * SW + tid], &g_order[j]);
        }
        CP_COMMIT();

        // ---- warp 0 walks super-window s ----
        if (wid == 0) {
            int base = s0 + s * SW;
            int lim = min(SW, s1 - base);
            int* rows = rbuf + (s & 1) * SW * K;
            int* ord  = obuf + (s & 3) * SW;

            for (int w0 = 0; w0 < lim; w0 += 32) {
                int m = min(32, lim - w0);
                int v = (lane < m) ? ord[w0 + lane] : 0;

                bool a = false;
                if (lane < m) {
                    int rel = v - s0;
                    a = !((bitmap[rel >> 5] >> (rel & 31)) & 1u);
                }
                unsigned alive = __ballot_sync(0xFFFFFFFFu, a);

                while (alive) {
                    int l = __ffs(alive) - 1;

                    if (useRing) {
                        const int* row = rows + (w0 + l) * 64;
                        int n0 = row[lane];
                        int n1 = row[lane + 32];

                        if (lane == 0) {
                            int cv = ord[w0 + l];
                            g_selLocal[s0 + cnt] = cv;   // fire-and-forget
                        }

                        int r0 = n0 - s0, r1 = n1 - s0;
                        bool f0 = (n0 >= 0) && ((unsigned)r0 < (unsigned)segLen);
                        bool f1 = (n1 >= 0) && ((unsigned)r1 < (unsigned)segLen);
                        unsigned wb0 = f0 ? bitmap[r0 >> 5] : ~0u;
                        unsigned wb1 = f1 ? bitmap[r1 >> 5] : ~0u;
                        if (f0 && !((wb0 >> (r0 & 31)) & 1u))
                            atomicOr(&bitmap[r0 >> 5], 1u << (r0 & 31));
                        if (f1 && !((wb1 >> (r1 & 31)) & 1u))
                            atomicOr(&bitmap[r1 >> 5], 1u << (r1 & 31));
                    } else {
                        int cv = __shfl_sync(0xFFFFFFFFu, v, l);
                        if (lane == 0) g_selLocal[s0 + cnt] = cv;
                        const int* row = neighs + (size_t)cv * K;
                        for (int t = lane; t < K; t += 32) {
                            int n = row[t];
                            int rel = n - s0;
                            if (n >= 0 && (unsigned)rel < (unsigned)segLen)
                                atomicOr(&bitmap[rel >> 5], 1u << (rel & 31));
                        }
                    }
                    cnt++;
                    __syncwarp();

                    bool a2 = false;
                    if (lane < m && lane > l) {
                        int rel = v - s0;
                        a2 = !((bitmap[rel >> 5] >> (rel & 31)) & 1u);
                    }
                    alive = __ballot_sync(0xFFFFFFFFu, a2);
                }
            }
        }
    }
    if (wid == 0 && lane == 0) g_segCount[seg] = cnt;
}

// ---------------- clustering phase 2: gg via parallel atomicMin ----------------
// 4 threads per order-position; active only for center positions.
// gg[u] = min local-cnt over centers adjacent (incl. self) to u.
__global__ void minK(const int* __restrict__ neighs, const int* __restrict__ rs,
                     int V, int K, int B) {
    int idx = blockIdx.x * blockDim.x + threadIdx.x;
    int p = idx >> 2, q = idx & 3;
    if (p >= V) return;
    int s = 0;
    while (s < B - 1 && p >= rs[s + 1]) s++;
    int s0 = rs[s];
    int local = p - s0;
    if (local >= g_segCount[s]) return;
    int segLen = rs[s + 1] - s0;
    int cv = g_selLocal[p];
    if (q == 0) atomicMin(&g_ggLocal[cv], local);    // center's own id
    int per = (K + 3) >> 2;
    int t0 = q * per, t1 = min(K, t0 + per);
    const int* row = neighs + (size_t)cv * K;
    for (int t = t0; t < t1; t++) {
        int n = row[t];
        int rel = n - s0;
        if (n >= 0 && (unsigned)rel < (unsigned)segLen)
            atomicMin(&g_ggLocal[n], local);
    }
}

// ---------------- finalize (float32 outputs) ----------------
__global__ void finalizeK(float* __restrict__ rsn, int B) {
    int a = 0;
    rsn[0] = 0.0f; g_rsn[0] = 0;
    for (int s = 0; s < B; s++) {
        a += g_segCount[s];
        rsn[s + 1] = (float)a;
        g_rsn[s + 1] = a;
    }
}

__global__ void fixK(const int* __restrict__ rs, float* __restrict__ sel,
                     float* __restrict__ gg, int V, int B) {
    int i = blockIdx.x * blockDim.x + threadIdx.x;
    if (i >= V) return;
    int s = 0;
    while (s < B - 1 && i >= rs[s + 1]) s++;
    gg[i] = (float)(g_ggLocal[i] + g_rsn[s]);      // local -> global cluster id
    int t = i - rs[s];
    if (t < g_segCount[s]) sel[g_rsn[s] + t] = (float)g_selLocal[i];
    if (i >= g_rsn[B]) sel[i] = -1.0f;             // padding
}

// ---------------- launch ----------------
extern "C" void kernel_launch(void* const* d_in, const int* in_sizes, int n_in,
                              void* d_out, int out_size) {
    // identify inputs by size: largest=neighs, middle=hier, smallest=row_splits
    long s[3] = { in_sizes[0], in_sizes[1], in_sizes[2] };
    int big = 0, small = 0;
    for (int i = 1; i < 3; i++) {
        if (s[i] > s[big]) big = i;
        if (s[i] < s[small]) small = i;
    }
    int mid = 3 - big - small;
    const int*   neighs = (const int*)d_in[big];
    const float* hier   = (const float*)d_in[mid];
    const int*   rs     = (const int*)d_in[small];

    int V = in_sizes[mid];
    int K = in_sizes[big] / V;
    int B = in_sizes[small] - 1;
    if (V > V_MAX || B > B_MAX || B < 1) return;

    float* out = (float*)d_out;
    float* sel = out;
    float* rsn = out + V;
    float* gg  = out + V + B + 1;

    int TILES = (V + TILE - 1) / TILE;
    if (TILES > TILES_MAX) return;

    int nb = (V + 255) / 256;
    packK<<<nb, 256>>>(hier, V);

    for (int p = 0; p < 4; p++) {
        int dir = p & 1;                  // 0: A->B, 1: B->A  (4 passes end in A)
        int shift = 32 + 8 * p;
        dim3 grid(TILES, B);
        histK<<<grid, 256>>>(dir, shift, TILES, rs);
        scanK<<<B, 256>>>(TILES, rs);
        scatterK<<<grid, 256>>>(dir, shift, TILES, rs);
    }
    extractK<<<nb, 256>>>(V);

    int bwMax = (V + 31) >> 5;
    bool useRing = (K == 64);
    size_t smemBytes = ((size_t)bwMax + 4 * SW) * 4
                     + (useRing ? (size_t)2 * SW * K * 4 : 0);

    // Set the >48KB smem opt-in only outside graph capture (attribute persists;
    // the un-captured correctness call always runs first).
    cudaStreamCaptureStatus cs = cudaStreamCaptureStatusNone;
    cudaStreamIsCapturing((cudaStream_t)0, &cs);
    if (cs == cudaStreamCaptureStatusNone) {
        cudaFuncSetAttribute(clusterK, cudaFuncAttributeMaxDynamicSharedMemorySize,
                             (int)smemBytes);
    }

    clusterK<<<B, 1024, smemBytes>>>(neighs, rs, V, K);

    minK<<<(V * 4 + 255) / 256, 256>>>(neighs, rs, V, K, B);
    finalizeK<<<1, 1>>>(rsn, B);
    fixK<<<nb, 256>>>(rs, sel, gg, V, B);
}